// round 1
// baseline (speedup 1.0000x reference)
#include <cuda_runtime.h>
#include <math_constants.h>

#define BB 32
#define SS 4096
#define HH 1024
#define KSPLIT 16
#define KCH (HH / KSPLIT)   // 64

// Scratch (allocation-free rule: __device__ globals)
__device__ float g_vp[KSPLIT][BB * HH];  // split-K partials of v = hid @ W  (2 MB)
__device__ float g_v[BB * HH];           // reduced v
__device__ float g_hb[BB];               // hid[b] . bias

// ---------------------------------------------------------------------------
// hb[b] = dot(hidden[b,:], bias)   — 1 block, warp w handles batch b=w
// ---------------------------------------------------------------------------
__global__ void hb_k(const float* __restrict__ hidden, const float* __restrict__ bias) {
    int w = threadIdx.x >> 5, lane = threadIdx.x & 31;
    float acc = 0.f;
    for (int k = lane; k < HH; k += 32)
        acc += hidden[w * HH + k] * bias[k];
    #pragma unroll
    for (int o = 16; o; o >>= 1) acc += __shfl_xor_sync(0xffffffffu, acc, o);
    if (lane == 0) g_hb[w] = acc;
}

// ---------------------------------------------------------------------------
// v partials: g_vp[ks][b*HH+h] = sum_{k in chunk ks} hidden[b,k] * W[k,h]
// grid (HH/256, KSPLIT), block 256. W reads coalesced over h.
// ---------------------------------------------------------------------------
__global__ void v_k(const float* __restrict__ hidden, const float* __restrict__ W) {
    __shared__ float sh[BB * KCH];  // 8 KB
    const int k0 = blockIdx.y * KCH;
    for (int i = threadIdx.x; i < BB * KCH; i += 256) {
        int b = i / KCH, k = i % KCH;
        sh[i] = hidden[b * HH + k0 + k];
    }
    __syncthreads();

    const int h = blockIdx.x * 256 + threadIdx.x;
    float acc[BB];
    #pragma unroll
    for (int b = 0; b < BB; b++) acc[b] = 0.f;

    for (int k = 0; k < KCH; k++) {
        float wv = W[(size_t)(k0 + k) * HH + h];
        #pragma unroll
        for (int b = 0; b < BB; b++) acc[b] += sh[b * KCH + k] * wv;
    }
    #pragma unroll
    for (int b = 0; b < BB; b++) g_vp[blockIdx.y][b * HH + h] = acc[b];
}

// Deterministic fixed-order reduction of the KSPLIT partials.
__global__ void vred_k() {
    int i = blockIdx.x * blockDim.x + threadIdx.x;
    if (i >= BB * HH) return;
    float s = 0.f;
    #pragma unroll
    for (int p = 0; p < KSPLIT; p++) s += g_vp[p][i];
    g_v[i] = s;
}

// ---------------------------------------------------------------------------
// Energies: out[b,s] = enc[b,s,:] . v[b,:] + hb[b]
// grid (SS/32, BB), block 256 = 8 warps x 4 rows/warp. HBM-bound kernel.
// ---------------------------------------------------------------------------
__global__ void score_k(const float* __restrict__ enc, float* __restrict__ out) {
    __shared__ float4 sv[HH / 4];  // v[b] staged, 4 KB
    const int b = blockIdx.y;
    for (int i = threadIdx.x; i < HH / 4; i += 256)
        sv[i] = reinterpret_cast<const float4*>(g_v + b * HH)[i];
    __syncthreads();

    const int w = threadIdx.x >> 5, lane = threadIdx.x & 31;
    const int s0 = blockIdx.x * 32 + w * 4;
    const float hb = g_hb[b];

    #pragma unroll
    for (int r = 0; r < 4; r++) {
        const int s = s0 + r;
        const float4* row =
            reinterpret_cast<const float4*>(enc + (size_t)b * SS * HH + (size_t)s * HH);
        float acc = 0.f;
        #pragma unroll
        for (int i = 0; i < 8; i++) {
            float4 e = row[lane + i * 32];
            float4 v = sv[lane + i * 32];
            acc += e.x * v.x + e.y * v.y + e.z * v.z + e.w * v.w;
        }
        #pragma unroll
        for (int o = 16; o; o >>= 1) acc += __shfl_xor_sync(0xffffffffu, acc, o);
        if (lane == 0) out[b * SS + s] = acc + hb;
    }
}

// ---------------------------------------------------------------------------
// Softmax in place over each row of 4096. grid BB, block 1024, 4 elems/thread.
// ---------------------------------------------------------------------------
__global__ void softmax_k(float* __restrict__ out) {
    __shared__ float red[32];
    __shared__ float bcast;
    float* row = out + blockIdx.x * SS;
    const int w = threadIdx.x >> 5, lane = threadIdx.x & 31;

    float vals[4];
    float mx = -CUDART_INF_F;
    #pragma unroll
    for (int i = 0; i < 4; i++) {
        vals[i] = row[threadIdx.x + i * 1024];
        mx = fmaxf(mx, vals[i]);
    }
    #pragma unroll
    for (int o = 16; o; o >>= 1) mx = fmaxf(mx, __shfl_xor_sync(0xffffffffu, mx, o));
    if (lane == 0) red[w] = mx;
    __syncthreads();
    if (w == 0) {
        float m = red[lane];
        #pragma unroll
        for (int o = 16; o; o >>= 1) m = fmaxf(m, __shfl_xor_sync(0xffffffffu, m, o));
        if (lane == 0) bcast = m;
    }
    __syncthreads();
    mx = bcast;

    float sum = 0.f;
    #pragma unroll
    for (int i = 0; i < 4; i++) {
        vals[i] = __expf(vals[i] - mx);
        sum += vals[i];
    }
    #pragma unroll
    for (int o = 16; o; o >>= 1) sum += __shfl_xor_sync(0xffffffffu, sum, o);
    if (lane == 0) red[w] = sum;
    __syncthreads();
    if (w == 0) {
        float s = red[lane];
        #pragma unroll
        for (int o = 16; o; o >>= 1) s += __shfl_xor_sync(0xffffffffu, s, o);
        if (lane == 0) bcast = s;
    }
    __syncthreads();
    const float inv = 1.0f / bcast;

    #pragma unroll
    for (int i = 0; i < 4; i++)
        row[threadIdx.x + i * 1024] = vals[i] * inv;
}

extern "C" void kernel_launch(void* const* d_in, const int* in_sizes, int n_in,
                              void* d_out, int out_size) {
    const float* hidden = (const float*)d_in[0];  // [B,1,H]
    const float* enc    = (const float*)d_in[1];  // [B,S,H]
    const float* W      = (const float*)d_in[2];  // [H,H]
    const float* bias   = (const float*)d_in[3];  // [H]
    float* out = (float*)d_out;                   // [B,S]

    hb_k<<<1, 1024>>>(hidden, bias);
    v_k<<<dim3(HH / 256, KSPLIT), 256>>>(hidden, W);
    vred_k<<<(BB * HH + 255) / 256, 256>>>();
    score_k<<<dim3(SS / 32, BB), 256>>>(enc, out);
    softmax_k<<<BB, 1024>>>(out);
}

// round 2
// speedup vs baseline: 1.3535x; 1.3535x over previous
#include <cuda_runtime.h>
#include <math_constants.h>

#define BB 32
#define SS 4096
#define HH 1024
#define KSPLIT 32
#define KCH (HH / KSPLIT)   // 32

// Scratch (allocation-free rule: __device__ globals)
__device__ float g_vp[KSPLIT][BB * HH];   // split-K partials of v = hid @ W (4 MB)
__device__ float g_v[BB * HH];            // reduced v
__device__ unsigned int g_cnt[BB];        // per-batch block-completion counters

// ---------------------------------------------------------------------------
// v partials: g_vp[ks][b*HH+h] = sum_{k in chunk ks} hidden[b,k] * W[k,h]
// grid (HH/256, KSPLIT) = (4, 32) = 128 blocks, block 256. W coalesced over h.
// NOTE: hid·bias term dropped entirely — it is constant per batch row and
// softmax is shift-invariant.
// ---------------------------------------------------------------------------
__global__ void v_k(const float* __restrict__ hidden, const float* __restrict__ W) {
    __shared__ float sh[BB * KCH];  // 4 KB
    const int k0 = blockIdx.y * KCH;
    for (int i = threadIdx.x; i < BB * KCH; i += 256) {
        int b = i / KCH, k = i % KCH;
        sh[i] = hidden[b * HH + k0 + k];
    }
    __syncthreads();

    const int h = blockIdx.x * 256 + threadIdx.x;
    float acc[BB];
    #pragma unroll
    for (int b = 0; b < BB; b++) acc[b] = 0.f;

    #pragma unroll 4
    for (int k = 0; k < KCH; k++) {
        float wv = W[(size_t)(k0 + k) * HH + h];
        #pragma unroll
        for (int b = 0; b < BB; b++) acc[b] += sh[b * KCH + k] * wv;
    }
    #pragma unroll
    for (int b = 0; b < BB; b++) g_vp[blockIdx.y][b * HH + h] = acc[b];
}

// Deterministic fixed-order reduction of the KSPLIT partials.
// Also resets the per-batch completion counters used by score_k's fused softmax.
__global__ void vred_k() {
    int i = blockIdx.x * blockDim.x + threadIdx.x;
    if (i < BB) g_cnt[i] = 0u;
    if (i >= BB * HH) return;
    float s = 0.f;
    #pragma unroll
    for (int p = 0; p < KSPLIT; p++) s += g_vp[p][i];
    g_v[i] = s;
}

// ---------------------------------------------------------------------------
// Energies + fused softmax.
// grid (SS/32, BB) = (128, 32), block 256 = 8 warps x 4 rows/warp.
// Phase 1 (all blocks): out[b,s] = enc[b,s,:] . v[b,:]
// Phase 2 (last block per batch row, elected via g_cnt): softmax in place.
// ---------------------------------------------------------------------------
__global__ void score_k(const float* __restrict__ enc, float* __restrict__ out) {
    __shared__ float4 sv[HH / 4];  // v[b] staged, 4 KB
    __shared__ float red[32];
    __shared__ float bcast;
    __shared__ unsigned int is_last;

    const int b = blockIdx.y;
    for (int i = threadIdx.x; i < HH / 4; i += 256)
        sv[i] = reinterpret_cast<const float4*>(g_v + b * HH)[i];
    __syncthreads();

    const int w = threadIdx.x >> 5, lane = threadIdx.x & 31;
    const int s0 = blockIdx.x * 32 + w * 4;

    #pragma unroll
    for (int r = 0; r < 4; r++) {
        const int s = s0 + r;
        const float4* row =
            reinterpret_cast<const float4*>(enc + (size_t)b * SS * HH + (size_t)s * HH);
        float acc = 0.f;
        #pragma unroll
        for (int i = 0; i < 8; i++) {
            float4 e = row[lane + i * 32];
            float4 v = sv[lane + i * 32];
            acc += e.x * v.x + e.y * v.y + e.z * v.z + e.w * v.w;
        }
        #pragma unroll
        for (int o = 16; o; o >>= 1) acc += __shfl_xor_sync(0xffffffffu, acc, o);
        if (lane == 0) out[b * SS + s] = acc;
    }

    // ---- release our writes, elect the last block for this batch row ----
    __threadfence();
    __syncthreads();
    if (threadIdx.x == 0)
        is_last = (atomicAdd(&g_cnt[b], 1u) == gridDim.x - 1u) ? 1u : 0u;
    __syncthreads();
    if (!is_last) return;
    __threadfence();  // acquire: all writers' stores now visible via L2

    // ---- softmax over out[b, 0:4096] with 256 threads, 16 elems/thread ----
    float* row = out + b * SS;
    float vals[16];
    float mx = -CUDART_INF_F;
    #pragma unroll
    for (int i = 0; i < 16; i++) {
        vals[i] = __ldcg(row + threadIdx.x + i * 256);  // L2-coherent read
        mx = fmaxf(mx, vals[i]);
    }
    #pragma unroll
    for (int o = 16; o; o >>= 1) mx = fmaxf(mx, __shfl_xor_sync(0xffffffffu, mx, o));
    if (lane == 0) red[w] = mx;
    __syncthreads();
    if (w == 0) {
        float m = (lane < 8) ? red[lane] : -CUDART_INF_F;
        #pragma unroll
        for (int o = 4; o; o >>= 1) m = fmaxf(m, __shfl_xor_sync(0xffffffffu, m, o));
        if (lane == 0) bcast = m;
    }
    __syncthreads();
    mx = bcast;

    float sum = 0.f;
    #pragma unroll
    for (int i = 0; i < 16; i++) {
        vals[i] = __expf(vals[i] - mx);
        sum += vals[i];
    }
    #pragma unroll
    for (int o = 16; o; o >>= 1) sum += __shfl_xor_sync(0xffffffffu, sum, o);
    if (lane == 0) red[w] = sum;
    __syncthreads();
    if (w == 0) {
        float s = (lane < 8) ? red[lane] : 0.f;
        #pragma unroll
        for (int o = 4; o; o >>= 1) s += __shfl_xor_sync(0xffffffffu, s, o);
        if (lane == 0) bcast = s;
    }
    __syncthreads();
    const float inv = 1.0f / bcast;

    #pragma unroll
    for (int i = 0; i < 16; i++)
        row[threadIdx.x + i * 256] = vals[i] * inv;
}

extern "C" void kernel_launch(void* const* d_in, const int* in_sizes, int n_in,
                              void* d_out, int out_size) {
    const float* hidden = (const float*)d_in[0];  // [B,1,H]
    const float* enc    = (const float*)d_in[1];  // [B,S,H]
    const float* W      = (const float*)d_in[2];  // [H,H]
    // d_in[3] = bias — unused: constant per row under softmax
    float* out = (float*)d_out;                   // [B,S]

    v_k<<<dim3(HH / 256, KSPLIT), 256>>>(hidden, W);
    vred_k<<<(BB * HH + 255) / 256, 256>>>();
    score_k<<<dim3(SS / 32, BB), 256>>>(enc, out);
}

// round 3
// speedup vs baseline: 1.3818x; 1.0209x over previous
#include <cuda_runtime.h>
#include <math_constants.h>

#define BB 32
#define SS 4096
#define HH 1024
#define KSPLIT 8
#define KCH (HH / KSPLIT)   // 128
#define BG 8                 // batches per v_k block
#define NBG (BB / BG)        // 4 batch groups

// Scratch (allocation-free rule: __device__ globals)
__device__ float g_vp[KSPLIT][BB * HH];   // split-K partials of v = hid @ W (1 MB)
__device__ float g_v[BB * HH];            // reduced v
__device__ unsigned int g_cnt[BB];        // per-batch block-completion counters

// ---------------------------------------------------------------------------
// v partials: g_vp[ks][b*HH+h] = sum_{k in chunk ks} hidden[b,k] * W[k,h]
// grid (HH/128, KSPLIT, NBG) = (8, 8, 4) = 256 blocks, block 128.
// acc[8] instead of acc[32] -> low regs, high occupancy (R2 v_k was
// latency-bound at 146 regs / 12% occ).
// bias term dropped: constant per batch row, softmax is shift-invariant.
// ---------------------------------------------------------------------------
__global__ void v_k(const float* __restrict__ hidden, const float* __restrict__ W) {
    __shared__ float sh[BG * KCH];  // 4 KB
    const int bg = blockIdx.z;
    const int k0 = blockIdx.y * KCH;

    for (int i = threadIdx.x; i < BG * KCH; i += 128) {
        int b = i / KCH, k = i % KCH;
        sh[i] = hidden[(bg * BG + b) * HH + k0 + k];
    }
    __syncthreads();

    const int h = blockIdx.x * 128 + threadIdx.x;
    float acc[BG];
    #pragma unroll
    for (int j = 0; j < BG; j++) acc[j] = 0.f;

    #pragma unroll 4
    for (int k = 0; k < KCH; k++) {
        float wv = W[(size_t)(k0 + k) * HH + h];
        #pragma unroll
        for (int j = 0; j < BG; j++) acc[j] += sh[j * KCH + k] * wv;
    }
    #pragma unroll
    for (int j = 0; j < BG; j++)
        g_vp[blockIdx.y][(bg * BG + j) * HH + h] = acc[j];
}

// Deterministic fixed-order reduction of the KSPLIT partials.
// Also resets the per-batch completion counters used by score_k's fused softmax.
__global__ void vred_k() {
    int i = blockIdx.x * blockDim.x + threadIdx.x;
    if (i < BB) g_cnt[i] = 0u;
    if (i >= BB * HH) return;
    float s = 0.f;
    #pragma unroll
    for (int p = 0; p < KSPLIT; p++) s += g_vp[p][i];
    g_v[i] = s;
}

// ---------------------------------------------------------------------------
// Energies + fused softmax.
// grid (SS/32, BB) = (128, 32), block 256 = 8 warps x 4 rows/warp.
// Phase 1 (all blocks): out[b,s] = enc[b,s,:] . v[b,:]  (enc streamed __ldcs)
// Phase 2 (last block per batch row, elected via g_cnt): softmax in place.
// ---------------------------------------------------------------------------
__global__ void score_k(const float* __restrict__ enc, float* __restrict__ out) {
    __shared__ float4 sv[HH / 4];  // v[b] staged, 4 KB
    __shared__ float red[32];
    __shared__ float bcast;
    __shared__ unsigned int is_last;

    const int b = blockIdx.y;
    for (int i = threadIdx.x; i < HH / 4; i += 256)
        sv[i] = reinterpret_cast<const float4*>(g_v + b * HH)[i];
    __syncthreads();

    const int w = threadIdx.x >> 5, lane = threadIdx.x & 31;
    const int s0 = blockIdx.x * 32 + w * 4;

    #pragma unroll
    for (int r = 0; r < 4; r++) {
        const int s = s0 + r;
        const float4* row =
            reinterpret_cast<const float4*>(enc + (size_t)b * SS * HH + (size_t)s * HH);
        float acc = 0.f;
        #pragma unroll
        for (int i = 0; i < 8; i++) {
            float4 e = __ldcs(row + lane + i * 32);  // streaming: read-once data
            float4 v = sv[lane + i * 32];
            acc += e.x * v.x + e.y * v.y + e.z * v.z + e.w * v.w;
        }
        #pragma unroll
        for (int o = 16; o; o >>= 1) acc += __shfl_xor_sync(0xffffffffu, acc, o);
        if (lane == 0) out[b * SS + s] = acc;
    }

    // ---- release our writes, elect the last block for this batch row ----
    __threadfence();
    __syncthreads();
    if (threadIdx.x == 0)
        is_last = (atomicAdd(&g_cnt[b], 1u) == gridDim.x - 1u) ? 1u : 0u;
    __syncthreads();
    if (!is_last) return;
    __threadfence();  // acquire: all writers' stores now visible via L2

    // ---- softmax over out[b, 0:4096] with 256 threads, 16 elems/thread ----
    float* row = out + b * SS;
    float vals[16];
    float mx = -CUDART_INF_F;
    #pragma unroll
    for (int i = 0; i < 16; i++) {
        vals[i] = __ldcg(row + threadIdx.x + i * 256);  // L2-coherent read
        mx = fmaxf(mx, vals[i]);
    }
    #pragma unroll
    for (int o = 16; o; o >>= 1) mx = fmaxf(mx, __shfl_xor_sync(0xffffffffu, mx, o));
    if (lane == 0) red[w] = mx;
    __syncthreads();
    if (w == 0) {
        float m = (lane < 8) ? red[lane] : -CUDART_INF_F;
        #pragma unroll
        for (int o = 4; o; o >>= 1) m = fmaxf(m, __shfl_xor_sync(0xffffffffu, m, o));
        if (lane == 0) bcast = m;
    }
    __syncthreads();
    mx = bcast;

    float sum = 0.f;
    #pragma unroll
    for (int i = 0; i < 16; i++) {
        vals[i] = __expf(vals[i] - mx);
        sum += vals[i];
    }
    #pragma unroll
    for (int o = 16; o; o >>= 1) sum += __shfl_xor_sync(0xffffffffu, sum, o);
    if (lane == 0) red[w] = sum;
    __syncthreads();
    if (w == 0) {
        float s = (lane < 8) ? red[lane] : 0.f;
        #pragma unroll
        for (int o = 4; o; o >>= 1) s += __shfl_xor_sync(0xffffffffu, s, o);
        if (lane == 0) bcast = s;
    }
    __syncthreads();
    const float inv = 1.0f / bcast;

    #pragma unroll
    for (int i = 0; i < 16; i++)
        row[threadIdx.x + i * 256] = vals[i] * inv;
}

extern "C" void kernel_launch(void* const* d_in, const int* in_sizes, int n_in,
                              void* d_out, int out_size) {
    const float* hidden = (const float*)d_in[0];  // [B,1,H]
    const float* enc    = (const float*)d_in[1];  // [B,S,H]
    const float* W      = (const float*)d_in[2];  // [H,H]
    // d_in[3] = bias — unused: constant per row under softmax
    float* out = (float*)d_out;                   // [B,S]

    v_k<<<dim3(HH / 128, KSPLIT, NBG), 128>>>(hidden, W);
    vred_k<<<(BB * HH + 255) / 256, 256>>>();
    score_k<<<dim3(SS / 32, BB), 256>>>(enc, out);
}